// round 6
// baseline (speedup 1.0000x reference)
#include <cuda_runtime.h>
#include <cuda_bf16.h>
#include <cstdint>

#define BB 200000      // batch size
#define NN 400000      // nodes = 2*BB
#define DD 128         // embedding dim
#define PITCH 136      // padded bf16 pitch for smem tiles
#define ACT 200000     // active rows (compact): positions [0,100k) u [200k,300k)
#define NBA 1563       // ceil(ACT/128)

// ---------------- scratch (device globals; no allocs allowed) ----------------
__device__ float g_deg[NN];                       // degree -> dinv (in place)
__device__ float g_H [(size_t)NN * DD];           // h = x @ W (active rows only)
__device__ float g_P0[(size_t)NN * DD];           // ping (agg buffer)
__device__ float g_P1[(size_t)NN * DD];           // pong (agg buffer)
__device__ __align__(16) char g_Wt_hi[3][128 * PITCH * 2];  // W^T bf16 hi, padded n-major
__device__ __align__(16) char g_Wt_lo[3][128 * PITCH * 2];  // W^T bf16 lo

// ---------------- helpers ----------------
__device__ __forceinline__ uint32_t smem_u32(const void* p) {
    uint32_t a;
    asm("{ .reg .u64 t; cvta.to.shared.u64 t, %1; cvt.u32.u64 %0, t; }" : "=r"(a) : "l"(p));
    return a;
}
__device__ __forceinline__ void red_add4(float* p, float4 v) {
    asm volatile("red.global.add.v4.f32 [%0], {%1,%2,%3,%4};"
                 :: "l"(p), "f"(v.x), "f"(v.y), "f"(v.z), "f"(v.w) : "memory");
}
__device__ __forceinline__ void cp_async16(uint32_t dst, const void* src) {
    asm volatile("cp.async.cg.shared.global [%0], [%1], 16;" :: "r"(dst), "l"(src) : "memory");
}
__device__ __forceinline__ void ldm_x4(uint32_t a, uint32_t& r0, uint32_t& r1,
                                       uint32_t& r2, uint32_t& r3) {
    asm volatile("ldmatrix.sync.aligned.m8n8.x4.shared.b16 {%0,%1,%2,%3}, [%4];"
                 : "=r"(r0), "=r"(r1), "=r"(r2), "=r"(r3) : "r"(a));
}
__device__ __forceinline__ void mma_bf16(float* c, const uint32_t* a, uint32_t b0, uint32_t b1) {
    asm volatile("mma.sync.aligned.m16n8k16.row.col.f32.bf16.bf16.f32 "
                 "{%0,%1,%2,%3}, {%4,%5,%6,%7}, {%8,%9}, {%0,%1,%2,%3};"
                 : "+f"(c[0]), "+f"(c[1]), "+f"(c[2]), "+f"(c[3])
                 : "r"(a[0]), "r"(a[1]), "r"(a[2]), "r"(a[3]), "r"(b0), "r"(b1));
}
__device__ __forceinline__ uint32_t pack_hi(float a, float b, uint32_t& lo) {
    __nv_bfloat16 h0 = __float2bfloat16(a), h1 = __float2bfloat16(b);
    __nv_bfloat16 l0 = __float2bfloat16(a - __bfloat162float(h0));
    __nv_bfloat16 l1 = __float2bfloat16(b - __bfloat162float(h1));
    lo = (uint32_t)__bfloat16_as_ushort(l0) | ((uint32_t)__bfloat16_as_ushort(l1) << 16);
    return (uint32_t)__bfloat16_as_ushort(h0) | ((uint32_t)__bfloat16_as_ushort(h1) << 16);
}

// shared A-tile offsets (common to both GEMM kernels)
#define SM_AHI  0
#define SM_ALO  (128 * PITCH * 2)          // 34816

// split a float4 row-chunk to bf16 hi/lo and store padded
__device__ __forceinline__ void split_store(char* smem, int row, int lane, float4 v) {
    uint2 hp, lp;
    hp.x = pack_hi(v.x, v.y, lp.x);
    hp.y = pack_hi(v.z, v.w, lp.y);
    uint32_t off = ((uint32_t)row * PITCH + (uint32_t)lane * 4) * 2;
    *(uint2*)(smem + SM_AHI + off) = hp;
    *(uint2*)(smem + SM_ALO + off) = lp;
}

// W tile async copy: 2176 uint4 each for hi and lo
__device__ __forceinline__ void copy_w_async(uint32_t dh, uint32_t dl, int layer) {
    const uint4* wh = (const uint4*)g_Wt_hi[layer];
    const uint4* wl = (const uint4*)g_Wt_lo[layer];
    int tid = threadIdx.x;
#pragma unroll
    for (int i = 0; i < 9; i++) {
        int idx = tid + i * 256;
        if (idx < 2176) { cp_async16(dh + idx * 16, wh + idx);
                          cp_async16(dl + idx * 16, wl + idx); }
    }
    asm volatile("cp.async.commit_group;" ::: "memory");
}

// ---------------- trivial kernels ----------------
__global__ void init_deg_kernel() {
    int i = blockIdx.x * blockDim.x + threadIdx.x;
    if (i < NN) g_deg[i] = 1.0f;
}
__global__ void count_deg_kernel(const int* __restrict__ ui, const int* __restrict__ ii) {
    int e = blockIdx.x * blockDim.x + threadIdx.x;
    if (e < BB) {
        atomicAdd(&g_deg[ii[e]], 1.0f);
        atomicAdd(&g_deg[ui[e] + BB], 1.0f);
    }
}
__global__ void dinv_kernel() {
    int i = blockIdx.x * blockDim.x + threadIdx.x;
    if (i < NN) g_deg[i] = 1.0f / sqrtf(g_deg[i]);
}
__global__ void wprep_kernel(const float* __restrict__ Wall) {
    int idx = blockIdx.x * blockDim.x + threadIdx.x;   // 3*128*128
    if (idx >= 3 * 128 * 128) return;
    int l = idx / 16384, r = idx % 16384;
    int k = r / 128, n = r % 128;
    float v = Wall[l * 16384 + k * 128 + n];
    __nv_bfloat16 hi = __float2bfloat16(v);
    __nv_bfloat16 lo = __float2bfloat16(v - __bfloat162float(hi));
    uint32_t off = ((uint32_t)n * PITCH + (uint32_t)k) * 2;
    *(__nv_bfloat16*)(g_Wt_hi[l] + off) = hi;
    *(__nv_bfloat16*)(g_Wt_lo[l] + off) = lo;
}

// ================= PASSIVE rows: fused 3-layer chain =================
// positions [100k,200k) u [300k,400k): deg=1, agg=h. out = relu3 chain.
#define PW_W0   (2 * 128 * PITCH * 2)   // 69632  (buf0 hi; lo at +34816)
#define PW_W1   (PW_W0 + 2 * 128 * PITCH * 2)   // 139264 (buf1)
#define PW_BIAS (PW_W1 + 2 * 128 * PITCH * 2)   // 208896
#define PW_TOTAL (PW_BIAS + 3 * 128 * 4)        // 210432

__global__ void __launch_bounds__(256, 1)
passive_kernel(const float* __restrict__ UT, const float* __restrict__ IT,
               const int* __restrict__ ui, const int* __restrict__ ii,
               const float* __restrict__ ball, float* __restrict__ out)
{
    extern __shared__ char smem[];
    uint32_t sb = smem_u32(smem);
    int tid = threadIdx.x, warp = tid >> 5, lane = tid & 31;
    int c0 = blockIdx.x * 128;

    copy_w_async(sb + PW_W0, sb + PW_W0 + 34816, 0);
    if (tid < 128) {
#pragma unroll
        for (int l = 0; l < 3; l++)
            ((float*)(smem + PW_BIAS))[l * 128 + tid] = ball[l * 128 + tid];
    }

    // gather A rows (layer-0 inputs for passive positions)
#pragma unroll
    for (int i = 0; i < 16; i++) {
        int row = warp * 16 + i;
        int c = c0 + row;
        float4 v = make_float4(0.f, 0.f, 0.f, 0.f);
        if (c < ACT) {
            if (c < 100000) v = ((const float4*)(UT + (size_t)ui[c + 100000] * DD))[lane];
            else            v = ((const float4*)(IT + (size_t)ii[c] * DD))[lane];
        }
        split_store(smem, row, lane, v);
    }
    asm volatile("cp.async.wait_group 0;" ::: "memory");
    __syncthreads();

    const float* bias = (const float*)(smem + PW_BIAS);
    int grp = lane >> 2, qc = 2 * (lane & 3);
    int arow = warp * 16 + (lane & 15);
    uint32_t aoff = sb + SM_AHI + ((uint32_t)arow * PITCH + (uint32_t)((lane >> 4) * 8)) * 2;
    uint32_t brel = ((uint32_t)((lane & 7) + ((lane >> 4) & 1) * 8) * PITCH
                   + (uint32_t)(((lane >> 3) & 1) * 8)) * 2;

#pragma unroll 1
    for (int stage = 0; stage < 3; stage++) {
        uint32_t wbase = sb + (stage & 1 ? PW_W1 : PW_W0);
        if (stage < 2)
            copy_w_async(sb + (stage & 1 ? PW_W0 : PW_W1),
                         sb + (stage & 1 ? PW_W0 : PW_W1) + 34816, stage + 1);

        float acc[16][4];
#pragma unroll
        for (int i = 0; i < 16; i++) { acc[i][0] = acc[i][1] = acc[i][2] = acc[i][3] = 0.f; }

#pragma unroll
        for (int k = 0; k < 8; k++) {
            uint32_t ah[4], al[4];
            uint32_t ak = aoff + (uint32_t)k * 32;
            ldm_x4(ak,                     ah[0], ah[1], ah[2], ah[3]);
            ldm_x4(ak + (SM_ALO - SM_AHI), al[0], al[1], al[2], al[3]);
#pragma unroll
            for (int t = 0; t < 8; t++) {
                uint32_t bh0, bh1, bh2, bh3, bl0, bl1, bl2, bl3;
                uint32_t bk = wbase + brel + (uint32_t)t * (16 * PITCH * 2) + (uint32_t)k * 32;
                ldm_x4(bk,         bh0, bh1, bh2, bh3);
                ldm_x4(bk + 34816, bl0, bl1, bl2, bl3);
                mma_bf16(acc[2 * t + 0], ah, bh0, bh1);
                mma_bf16(acc[2 * t + 1], ah, bh2, bh3);
                mma_bf16(acc[2 * t + 0], al, bh0, bh1);
                mma_bf16(acc[2 * t + 1], al, bh2, bh3);
                mma_bf16(acc[2 * t + 0], ah, bl0, bl1);
                mma_bf16(acc[2 * t + 1], ah, bl2, bl3);
            }
        }

        int rAl = warp * 16 + grp, rBl = rAl + 8;
        if (stage < 2) {
            __syncthreads();   // everyone done reading A
#pragma unroll
            for (int nt = 0; nt < 16; nt++) {
                int col = nt * 8 + qc;
                float bx = bias[stage * 128 + col], by = bias[stage * 128 + col + 1];
                float v0 = fmaxf(acc[nt][0] + bx, 0.f), v1 = fmaxf(acc[nt][1] + by, 0.f);
                float v2 = fmaxf(acc[nt][2] + bx, 0.f), v3 = fmaxf(acc[nt][3] + by, 0.f);
                uint32_t loA, loB;
                uint32_t hiA = pack_hi(v0, v1, loA);
                uint32_t hiB = pack_hi(v2, v3, loB);
                uint32_t offA = ((uint32_t)rAl * PITCH + (uint32_t)col) * 2;
                uint32_t offB = ((uint32_t)rBl * PITCH + (uint32_t)col) * 2;
                *(uint32_t*)(smem + SM_AHI + offA) = hiA;
                *(uint32_t*)(smem + SM_ALO + offA) = loA;
                *(uint32_t*)(smem + SM_AHI + offB) = hiB;
                *(uint32_t*)(smem + SM_ALO + offB) = loB;
            }
            asm volatile("cp.async.wait_group 0;" ::: "memory");
            __syncthreads();
        } else {
            int cA = c0 + rAl, cB = c0 + rBl;
            bool vA = cA < ACT, vB = cB < ACT;
            float* oA = vA ? out + ((size_t)cA + (cA < 100000 ? 100000 : 200000)) * DD : nullptr;
            float* oB = vB ? out + ((size_t)cB + (cB < 100000 ? 100000 : 200000)) * DD : nullptr;
#pragma unroll
            for (int nt = 0; nt < 16; nt++) {
                int col = nt * 8 + qc;
                float bx = bias[256 + col], by = bias[256 + col + 1];
                if (vA) *(float2*)(oA + col) =
                    make_float2(fmaxf(acc[nt][0] + bx, 0.f), fmaxf(acc[nt][1] + by, 0.f));
                if (vB) *(float2*)(oB + col) =
                    make_float2(fmaxf(acc[nt][2] + bx, 0.f), fmaxf(acc[nt][3] + by, 0.f));
            }
        }
    }
}

// ================= ACTIVE rows: per-layer GEMM =================
#define SM_WHI  (2 * 128 * PITCH * 2)      // 69632
#define SM_WLO  (3 * 128 * PITCH * 2)      // 104448
#define SM_BIAS (4 * 128 * PITCH * 2)      // 139264
#define SM_TOTAL (SM_BIAS + 512)

__global__ void __launch_bounds__(256, 1)
tc_gemm_kernel(const float* __restrict__ X,
               const int* __restrict__ ui, const int* __restrict__ ii,
               const float* __restrict__ IT, int gather0,
               int layer, const float* __restrict__ bprev, int has_act,
               const float* __restrict__ dinv,
               float* __restrict__ H, float* __restrict__ AGG)
{
    extern __shared__ char smem[];
    uint32_t sb = smem_u32(smem);
    int tid = threadIdx.x, warp = tid >> 5, lane = tid & 31;
    int c0 = blockIdx.x * 128;

    copy_w_async(sb + SM_WHI, sb + SM_WLO, layer);
    if (tid < 128) ((float*)(smem + SM_BIAS))[tid] = has_act ? bprev[tid] : 0.0f;
    __syncthreads();   // bias visible (W copy in flight)
    const float* bsm = (const float*)(smem + SM_BIAS);

    // A tile: compact index c -> position pos
#pragma unroll
    for (int i = 0; i < 16; i++) {
        int row = warp * 16 + i;
        int c = c0 + row;
        float4 v = make_float4(0.f, 0.f, 0.f, 0.f);
        if (c < ACT) {
            if (gather0) {
                if (c < 100000) v = ((const float4*)(X  + (size_t)ui[c] * DD))[lane];
                else            v = ((const float4*)(IT + (size_t)ii[c - 100000] * DD))[lane];
            } else {
                size_t pos = (size_t)c + (c < 100000 ? 0 : 100000);
                v = ((const float4*)(X + pos * DD))[lane];
            }
            if (has_act) {
                int cc = lane * 4;
                v.x = fmaxf(v.x + bsm[cc + 0], 0.0f);
                v.y = fmaxf(v.y + bsm[cc + 1], 0.0f);
                v.z = fmaxf(v.z + bsm[cc + 2], 0.0f);
                v.w = fmaxf(v.w + bsm[cc + 3], 0.0f);
            }
        }
        split_store(smem, row, lane, v);
    }
    asm volatile("cp.async.wait_group 0;" ::: "memory");
    __syncthreads();

    int arow = warp * 16 + (lane & 15);
    uint32_t aoff = sb + SM_AHI + ((uint32_t)arow * PITCH + (uint32_t)((lane >> 4) * 8)) * 2;
    int brow = (lane & 7) + ((lane >> 4) & 1) * 8;
    uint32_t boff = sb + SM_WHI + ((uint32_t)brow * PITCH + (uint32_t)(((lane >> 3) & 1) * 8)) * 2;

    float acc[16][4];
#pragma unroll
    for (int i = 0; i < 16; i++) { acc[i][0] = acc[i][1] = acc[i][2] = acc[i][3] = 0.f; }

#pragma unroll
    for (int k = 0; k < 8; k++) {
        uint32_t ah[4], al[4];
        uint32_t ak = aoff + (uint32_t)k * 32;
        ldm_x4(ak,                     ah[0], ah[1], ah[2], ah[3]);
        ldm_x4(ak + (SM_ALO - SM_AHI), al[0], al[1], al[2], al[3]);
#pragma unroll
        for (int t = 0; t < 8; t++) {
            uint32_t bh0, bh1, bh2, bh3, bl0, bl1, bl2, bl3;
            uint32_t bk = boff + (uint32_t)t * (16 * PITCH * 2) + (uint32_t)k * 32;
            ldm_x4(bk,                     bh0, bh1, bh2, bh3);
            ldm_x4(bk + (SM_WLO - SM_WHI), bl0, bl1, bl2, bl3);
            mma_bf16(acc[2 * t + 0], ah, bh0, bh1);
            mma_bf16(acc[2 * t + 1], ah, bh2, bh3);
            mma_bf16(acc[2 * t + 0], al, bh0, bh1);
            mma_bf16(acc[2 * t + 1], al, bh2, bh3);
            mma_bf16(acc[2 * t + 0], ah, bl0, bl1);
            mma_bf16(acc[2 * t + 1], ah, bl2, bl3);
        }
    }

    // epilogue: H and AGG at mapped positions
    int grp = lane >> 2, qc = 2 * (lane & 3);
    int cA = c0 + warp * 16 + grp, cB = cA + 8;
    bool vA = cA < ACT, vB = cB < ACT;
    size_t posA = (size_t)cA + (cA < 100000 ? 0 : 100000);
    size_t posB = (size_t)cB + (cB < 100000 ? 0 : 100000);
    float dA = vA ? dinv[posA] : 0.f; dA *= dA;
    float dB = vB ? dinv[posB] : 0.f; dB *= dB;
    float* Hr0 = H + posA * DD;
    float* Hr1 = H + posB * DD;
    float* Gr0 = AGG + posA * DD;
    float* Gr1 = AGG + posB * DD;
#pragma unroll
    for (int nt = 0; nt < 16; nt++) {
        int col = nt * 8 + qc;
        float2 v0 = make_float2(acc[nt][0], acc[nt][1]);
        float2 v1 = make_float2(acc[nt][2], acc[nt][3]);
        if (vA) { *(float2*)(Hr0 + col) = v0;
                  *(float2*)(Gr0 + col) = make_float2(v0.x * dA, v0.y * dA); }
        if (vB) { *(float2*)(Hr1 + col) = v1;
                  *(float2*)(Gr1 + col) = make_float2(v1.x * dB, v1.y * dB); }
    }
}

// ---------------- scatter / final ----------------
__global__ void scatter_kernel(const int* __restrict__ ui, const int* __restrict__ ii,
                               const float* __restrict__ H, const float* __restrict__ dinv,
                               float* __restrict__ AGG) {
    int t = blockIdx.x * blockDim.x + threadIdx.x;
    int e = t >> 5;
    if (e >= BB) return;
    int lane = t & 31;
    int a = ii[e];
    int b = ui[e] + BB;
    float norm = dinv[a] * dinv[b];
    float4 va = ((const float4*)(H + (size_t)b * DD))[lane];
    float4 vb = ((const float4*)(H + (size_t)a * DD))[lane];
    va.x *= norm; va.y *= norm; va.z *= norm; va.w *= norm;
    vb.x *= norm; vb.y *= norm; vb.z *= norm; vb.w *= norm;
    red_add4(AGG + (size_t)a * DD + lane * 4, va);
    red_add4(AGG + (size_t)b * DD + lane * 4, vb);
}

// final for ACTIVE rows only (passive written by passive_kernel)
__global__ void final_active_kernel(const float* __restrict__ Z, const float* __restrict__ b,
                                    float* __restrict__ out) {
    int idx = blockIdx.x * blockDim.x + threadIdx.x;   // over ACT*32 float4
    if (idx >= ACT * 32) return;
    int c = idx >> 5, c4 = idx & 31;
    size_t pos = (size_t)c + (c < 100000 ? 0 : 100000);
    float4 v = ((const float4*)(Z + pos * DD))[c4];
    float4 bb = ((const float4*)b)[c4];
    v.x = fmaxf(v.x + bb.x, 0.0f);
    v.y = fmaxf(v.y + bb.y, 0.0f);
    v.z = fmaxf(v.z + bb.z, 0.0f);
    v.w = fmaxf(v.w + bb.w, 0.0f);
    ((float4*)(out + pos * DD))[c4] = v;
}

extern "C" void kernel_launch(void* const* d_in, const int* in_sizes, int n_in,
                              void* d_out, int out_size) {
    const int*   ui   = (const int*)d_in[0];
    const int*   ii   = (const int*)d_in[1];
    const float* UT   = (const float*)d_in[2];
    const float* IT   = (const float*)d_in[3];
    const float* Wall = (const float*)d_in[4];
    const float* ball = (const float*)d_in[5];
    float* out = (float*)d_out;

    float *deg, *H, *P0, *P1;
    cudaGetSymbolAddress((void**)&deg, g_deg);
    cudaGetSymbolAddress((void**)&H,   g_H);
    cudaGetSymbolAddress((void**)&P0,  g_P0);
    cudaGetSymbolAddress((void**)&P1,  g_P1);

    cudaFuncSetAttribute(tc_gemm_kernel, cudaFuncAttributeMaxDynamicSharedMemorySize, SM_TOTAL);
    cudaFuncSetAttribute(passive_kernel, cudaFuncAttributeMaxDynamicSharedMemorySize, PW_TOTAL);

    init_deg_kernel<<<(NN + 255) / 256, 256>>>();
    count_deg_kernel<<<(BB + 255) / 256, 256>>>(ui, ii);
    dinv_kernel<<<(NN + 255) / 256, 256>>>();
    wprep_kernel<<<(3 * 128 * 128 + 255) / 256, 256>>>(Wall);

    // passive half: fused 3-layer chain straight to output
    passive_kernel<<<NBA, 256, PW_TOTAL>>>(UT, IT, ui, ii, ball, out);

    // active half: per-layer GEMM + scatter
    tc_gemm_kernel<<<NBA, 256, SM_TOTAL>>>(UT, ui, ii, IT, 1, 0, nullptr, 0, deg, H, P0);
    scatter_kernel<<<(BB * 32 + 255) / 256, 256>>>(ui, ii, H, deg, P0);
    tc_gemm_kernel<<<NBA, 256, SM_TOTAL>>>(P0, ui, ii, nullptr, 0, 1, ball, 1, deg, H, P1);
    scatter_kernel<<<(BB * 32 + 255) / 256, 256>>>(ui, ii, H, deg, P1);
    tc_gemm_kernel<<<NBA, 256, SM_TOTAL>>>(P1, ui, ii, nullptr, 0, 2, ball + DD, 1, deg, H, P0);
    scatter_kernel<<<(BB * 32 + 255) / 256, 256>>>(ui, ii, H, deg, P0);

    final_active_kernel<<<(ACT * 32 + 255) / 256, 256>>>(P0, ball + 2 * DD, out);
}

// round 7
// speedup vs baseline: 1.1774x; 1.1774x over previous
#include <cuda_runtime.h>
#include <cuda_bf16.h>
#include <cstdint>

#define BB 200000      // batch size
#define NN 400000      // nodes = 2*BB
#define DD 128         // embedding dim
#define PITCH 136      // padded bf16 pitch for smem tiles
#define TM 64          // GEMM tile rows per CTA
#define NTHR 128       // threads per GEMM CTA (4 warps)

// ---------------- scratch (device globals; no allocs allowed) ----------------
__device__ float g_deg[NN];                       // degree -> dinv (in place)
__device__ float g_H [(size_t)NN * DD];           // h = x @ W
__device__ float g_P0[(size_t)NN * DD];           // ping (agg buffer)
__device__ float g_P1[(size_t)NN * DD];           // pong (agg buffer)
__device__ __align__(16) char g_Wt_hi[3][128 * PITCH * 2];  // W^T bf16 hi, padded n-major
__device__ __align__(16) char g_Wt_lo[3][128 * PITCH * 2];  // W^T bf16 lo

// ---------------- helpers ----------------
__device__ __forceinline__ uint32_t smem_u32(const void* p) {
    uint32_t a;
    asm("{ .reg .u64 t; cvta.to.shared.u64 t, %1; cvt.u32.u64 %0, t; }" : "=r"(a) : "l"(p));
    return a;
}
__device__ __forceinline__ void red_add4(float* p, float4 v) {
    asm volatile("red.global.add.v4.f32 [%0], {%1,%2,%3,%4};"
                 :: "l"(p), "f"(v.x), "f"(v.y), "f"(v.z), "f"(v.w) : "memory");
}
__device__ __forceinline__ void cp_async16(uint32_t dst, const void* src) {
    asm volatile("cp.async.cg.shared.global [%0], [%1], 16;" :: "r"(dst), "l"(src) : "memory");
}
__device__ __forceinline__ void ldm_x4(uint32_t a, uint32_t& r0, uint32_t& r1,
                                       uint32_t& r2, uint32_t& r3) {
    asm volatile("ldmatrix.sync.aligned.m8n8.x4.shared.b16 {%0,%1,%2,%3}, [%4];"
                 : "=r"(r0), "=r"(r1), "=r"(r2), "=r"(r3) : "r"(a));
}
__device__ __forceinline__ void mma_bf16(float* c, const uint32_t* a, uint32_t b0, uint32_t b1) {
    asm volatile("mma.sync.aligned.m16n8k16.row.col.f32.bf16.bf16.f32 "
                 "{%0,%1,%2,%3}, {%4,%5,%6,%7}, {%8,%9}, {%0,%1,%2,%3};"
                 : "+f"(c[0]), "+f"(c[1]), "+f"(c[2]), "+f"(c[3])
                 : "r"(a[0]), "r"(a[1]), "r"(a[2]), "r"(a[3]), "r"(b0), "r"(b1));
}
// node ids that appear as edge endpoints: [0,100k) u [200k,300k)
__device__ __forceinline__ bool h_useful(size_t r) {
    return (r < 100000) || (r >= 200000 && r < 300000);
}

// ---------------- trivial kernels ----------------
__global__ void init_deg_kernel() {
    int i = blockIdx.x * blockDim.x + threadIdx.x;
    if (i < NN) g_deg[i] = 1.0f;
}
__global__ void count_deg_kernel(const int* __restrict__ ui, const int* __restrict__ ii) {
    int e = blockIdx.x * blockDim.x + threadIdx.x;
    if (e < BB) {
        atomicAdd(&g_deg[ii[e]], 1.0f);
        atomicAdd(&g_deg[ui[e] + BB], 1.0f);
    }
}
__global__ void dinv_kernel() {
    int i = blockIdx.x * blockDim.x + threadIdx.x;
    if (i < NN) g_deg[i] = 1.0f / sqrtf(g_deg[i]);
}

// W^T (Wt[n][k] = W[k][n]) -> bf16 hi/lo, padded pitch
__global__ void wprep_kernel(const float* __restrict__ Wall) {
    int idx = blockIdx.x * blockDim.x + threadIdx.x;   // 3*128*128
    if (idx >= 3 * 128 * 128) return;
    int l = idx / 16384, r = idx % 16384;
    int k = r / 128, n = r % 128;
    float v = Wall[l * 16384 + k * 128 + n];
    __nv_bfloat16 hi = __float2bfloat16(v);
    __nv_bfloat16 lo = __float2bfloat16(v - __bfloat162float(hi));
    uint32_t off = ((uint32_t)n * PITCH + (uint32_t)k) * 2;
    *(__nv_bfloat16*)(g_Wt_hi[l] + off) = hi;
    *(__nv_bfloat16*)(g_Wt_lo[l] + off) = lo;
}

// ---------------- HMMA GEMM ----------------
// H = act(X) @ W ; AGG = dinv^2 * H.  TM=64 rows/CTA, 128 threads (4 warps).
// 2 CTAs/SM: A-load & epilogue of one CTA overlap MMA of the other.
#define SM_AHI  0
#define SM_ALO  (TM * PITCH * 2)               // 17408
#define SM_WHI  (2 * TM * PITCH * 2)           // 34816
#define SM_WLO  (SM_WHI + 128 * PITCH * 2)     // 69632
#define SM_BIAS (SM_WLO + 128 * PITCH * 2)     // 104448
#define SM_TOTAL (SM_BIAS + 512)               // 104960

__global__ void __launch_bounds__(NTHR, 2)
tc_gemm_kernel(const float* __restrict__ X,
               const int* __restrict__ ui, const int* __restrict__ ii,
               const float* __restrict__ IT, int gather0,
               int layer, const float* __restrict__ bprev, int has_act,
               const float* __restrict__ dinv,
               float* __restrict__ H, float* __restrict__ AGG)
{
    extern __shared__ char smem[];
    uint32_t sb = smem_u32(smem);
    int tid = threadIdx.x, warp = tid >> 5, lane = tid & 31;
    size_t row0 = (size_t)blockIdx.x * TM;

    // async copy of padded W tiles (2176 uint4 each; 17 iters x 128 thr exactly)
    {
        const uint4* wh = (const uint4*)g_Wt_hi[layer];
        const uint4* wl = (const uint4*)g_Wt_lo[layer];
        uint32_t dh = sb + SM_WHI, dl = sb + SM_WLO;
#pragma unroll
        for (int i = 0; i < 17; i++) {
            int idx = tid + i * NTHR;
            cp_async16(dh + idx * 16, wh + idx);
            cp_async16(dl + idx * 16, wl + idx);
        }
        asm volatile("cp.async.commit_group;" ::: "memory");
    }
    ((float*)(smem + SM_BIAS))[tid] = has_act ? bprev[tid] : 0.0f;
    __syncthreads();   // bias visible (W copy still in flight)
    const float* bsm = (const float*)(smem + SM_BIAS);

    // A tile: load (optionally gathered), act, bf16 hi/lo split, store padded
#pragma unroll
    for (int i = 0; i < 16; i++) {
        int row = warp * 16 + i;
        size_t grow = row0 + row;
        float4 v;
        if (gather0) {
            if (grow < BB) v = ((const float4*)(X  + (size_t)ui[grow] * DD))[lane];
            else           v = ((const float4*)(IT + (size_t)ii[grow - BB] * DD))[lane];
        } else {
            v = ((const float4*)(X + grow * DD))[lane];
        }
        if (has_act) {
            int c = lane * 4;
            v.x = fmaxf(v.x + bsm[c + 0], 0.0f);
            v.y = fmaxf(v.y + bsm[c + 1], 0.0f);
            v.z = fmaxf(v.z + bsm[c + 2], 0.0f);
            v.w = fmaxf(v.w + bsm[c + 3], 0.0f);
        }
        __nv_bfloat16 h0 = __float2bfloat16(v.x), h1 = __float2bfloat16(v.y);
        __nv_bfloat16 h2 = __float2bfloat16(v.z), h3 = __float2bfloat16(v.w);
        __nv_bfloat16 l0 = __float2bfloat16(v.x - __bfloat162float(h0));
        __nv_bfloat16 l1 = __float2bfloat16(v.y - __bfloat162float(h1));
        __nv_bfloat16 l2 = __float2bfloat16(v.z - __bfloat162float(h2));
        __nv_bfloat16 l3 = __float2bfloat16(v.w - __bfloat162float(h3));
        uint2 hp, lp;
        hp.x = (uint32_t)__bfloat16_as_ushort(h0) | ((uint32_t)__bfloat16_as_ushort(h1) << 16);
        hp.y = (uint32_t)__bfloat16_as_ushort(h2) | ((uint32_t)__bfloat16_as_ushort(h3) << 16);
        lp.x = (uint32_t)__bfloat16_as_ushort(l0) | ((uint32_t)__bfloat16_as_ushort(l1) << 16);
        lp.y = (uint32_t)__bfloat16_as_ushort(l2) | ((uint32_t)__bfloat16_as_ushort(l3) << 16);
        uint32_t off = ((uint32_t)row * PITCH + (uint32_t)lane * 4) * 2;
        *(uint2*)(smem + SM_AHI + off) = hp;
        *(uint2*)(smem + SM_ALO + off) = lp;
    }
    asm volatile("cp.async.wait_group 0;" ::: "memory");
    __syncthreads();

    // ldmatrix lane addressing
    int arow = warp * 16 + (lane & 15);
    uint32_t aoff = sb + SM_AHI + ((uint32_t)arow * PITCH + (uint32_t)((lane >> 4) * 8)) * 2;
    int brow = (lane & 7) + ((lane >> 4) & 1) * 8;
    uint32_t boff = sb + SM_WHI + ((uint32_t)brow * PITCH + (uint32_t)(((lane >> 3) & 1) * 8)) * 2;

    float acc[16][4];
#pragma unroll
    for (int i = 0; i < 16; i++) { acc[i][0] = acc[i][1] = acc[i][2] = acc[i][3] = 0.f; }

#pragma unroll
    for (int k = 0; k < 8; k++) {
        uint32_t ah[4], al[4];
        uint32_t ak = aoff + (uint32_t)k * 32;
        ldm_x4(ak, ah[0], ah[1], ah[2], ah[3]);
        ldm_x4(ak + (SM_ALO - SM_AHI), al[0], al[1], al[2], al[3]);
#pragma unroll
        for (int t = 0; t < 8; t++) {
            uint32_t bh0, bh1, bh2, bh3, bl0, bl1, bl2, bl3;
            uint32_t bk = boff + (uint32_t)t * (16 * PITCH * 2) + (uint32_t)k * 32;
            ldm_x4(bk,                     bh0, bh1, bh2, bh3);
            ldm_x4(bk + (SM_WLO - SM_WHI), bl0, bl1, bl2, bl3);
            mma_bf16(acc[2 * t + 0], ah, bh0, bh1);
            mma_bf16(acc[2 * t + 1], ah, bh2, bh3);
            mma_bf16(acc[2 * t + 0], al, bh0, bh1);
            mma_bf16(acc[2 * t + 1], al, bh2, bh3);
            mma_bf16(acc[2 * t + 0], ah, bl0, bl1);
            mma_bf16(acc[2 * t + 1], ah, bl2, bl3);
        }
    }

    // epilogue straight from fragments; H written only for useful node ids
    int grp = lane >> 2, qc = 2 * (lane & 3);
    size_t rA = row0 + warp * 16 + grp;
    size_t rB = rA + 8;
    float dA = dinv[rA]; dA *= dA;
    float dB = dinv[rB]; dB *= dB;
    bool uA = h_useful(rA), uB = h_useful(rB);
    float* Hr0 = H + rA * DD;
    float* Hr1 = H + rB * DD;
    float* Gr0 = AGG + rA * DD;
    float* Gr1 = AGG + rB * DD;
#pragma unroll
    for (int nt = 0; nt < 16; nt++) {
        int col = nt * 8 + qc;
        float2 v0 = make_float2(acc[nt][0], acc[nt][1]);
        float2 v1 = make_float2(acc[nt][2], acc[nt][3]);
        if (uA) *(float2*)(Hr0 + col) = v0;
        if (uB) *(float2*)(Hr1 + col) = v1;
        *(float2*)(Gr0 + col) = make_float2(v0.x * dA, v0.y * dA);
        *(float2*)(Gr1 + col) = make_float2(v1.x * dB, v1.y * dB);
    }
}

// ---------------- scatter / final ----------------
__global__ void scatter_kernel(const int* __restrict__ ui, const int* __restrict__ ii,
                               const float* __restrict__ H, const float* __restrict__ dinv,
                               float* __restrict__ AGG) {
    int t = blockIdx.x * blockDim.x + threadIdx.x;
    int e = t >> 5;
    if (e >= BB) return;
    int lane = t & 31;
    int a = ii[e];
    int b = ui[e] + BB;
    float norm = dinv[a] * dinv[b];
    float4 va = ((const float4*)(H + (size_t)b * DD))[lane];
    float4 vb = ((const float4*)(H + (size_t)a * DD))[lane];
    va.x *= norm; va.y *= norm; va.z *= norm; va.w *= norm;
    vb.x *= norm; vb.y *= norm; vb.z *= norm; vb.w *= norm;
    red_add4(AGG + (size_t)a * DD + lane * 4, va);
    red_add4(AGG + (size_t)b * DD + lane * 4, vb);
}

__global__ void final_kernel(const float* __restrict__ Z, const float* __restrict__ b,
                             float* __restrict__ out) {
    int idx = blockIdx.x * blockDim.x + threadIdx.x;
    if (idx >= NN * 32) return;
    int c = idx & 31;
    float4 v = ((const float4*)Z)[idx];
    float4 bb = ((const float4*)b)[c];
    v.x = fmaxf(v.x + bb.x, 0.0f);
    v.y = fmaxf(v.y + bb.y, 0.0f);
    v.z = fmaxf(v.z + bb.z, 0.0f);
    v.w = fmaxf(v.w + bb.w, 0.0f);
    ((float4*)out)[idx] = v;
}

extern "C" void kernel_launch(void* const* d_in, const int* in_sizes, int n_in,
                              void* d_out, int out_size) {
    const int*   ui   = (const int*)d_in[0];
    const int*   ii   = (const int*)d_in[1];
    const float* UT   = (const float*)d_in[2];
    const float* IT   = (const float*)d_in[3];
    const float* Wall = (const float*)d_in[4];
    const float* ball = (const float*)d_in[5];
    float* out = (float*)d_out;

    float *deg, *H, *P0, *P1;
    cudaGetSymbolAddress((void**)&deg, g_deg);
    cudaGetSymbolAddress((void**)&H,   g_H);
    cudaGetSymbolAddress((void**)&P0,  g_P0);
    cudaGetSymbolAddress((void**)&P1,  g_P1);

    cudaFuncSetAttribute(tc_gemm_kernel, cudaFuncAttributeMaxDynamicSharedMemorySize, SM_TOTAL);

    init_deg_kernel<<<(NN + 255) / 256, 256>>>();
    count_deg_kernel<<<(BB + 255) / 256, 256>>>(ui, ii);
    dinv_kernel<<<(NN + 255) / 256, 256>>>();
    wprep_kernel<<<(3 * 128 * 128 + 255) / 256, 256>>>(Wall);

    // layer 0: fused gather from tables (no act)
    tc_gemm_kernel<<<NN / TM, NTHR, SM_TOTAL>>>(UT, ui, ii, IT, 1, 0, nullptr, 0, deg, H, P0);
    scatter_kernel<<<(BB * 32 + 255) / 256, 256>>>(ui, ii, H, deg, P0);
    // layer 1: relu(P0 + b0)
    tc_gemm_kernel<<<NN / TM, NTHR, SM_TOTAL>>>(P0, ui, ii, nullptr, 0, 1, ball, 1, deg, H, P1);
    scatter_kernel<<<(BB * 32 + 255) / 256, 256>>>(ui, ii, H, deg, P1);
    // layer 2: relu(P1 + b1)
    tc_gemm_kernel<<<NN / TM, NTHR, SM_TOTAL>>>(P1, ui, ii, nullptr, 0, 2, ball + DD, 1, deg, H, P0);
    scatter_kernel<<<(BB * 32 + 255) / 256, 256>>>(ui, ii, H, deg, P0);

    final_kernel<<<(NN * 32 + 255) / 256, 256>>>(P0, ball + 2 * DD, out);
}